// round 1
// baseline (speedup 1.0000x reference)
#include <cuda_runtime.h>
#include <math.h>

#define Bsz 512
#define Tsz 512
#define Dsz 256

// out = [p (512) | T_event (512x513) | L_t (512x256) | M_t (512)]
#define OFF_TE 512
#define OFF_L  (512 + 512*513)
#define OFF_M  (OFF_L + 512*256)

__device__ __align__(16) float g_q[Bsz*Dsz];
__device__ __align__(16) float g_Q[Bsz*Dsz];
__device__ __align__(16) float g_u[Bsz*Dsz];
__device__ __align__(16) float g_y[Bsz*Dsz];
__device__ float g_tmax[Bsz];

// ---------------- Kernel 1: masked mean pool q[b,:], t_max[b] ----------------
__global__ void k1_pool(const float* __restrict__ wf, const float* __restrict__ ts,
                        const unsigned char* __restrict__ pad) {
    int b = blockIdx.x, tid = threadIdx.x;
    __shared__ float s_valid[Tsz];
    __shared__ float rmax[256], rsum[256];
    __shared__ float4 s_acc[4][64];

    float lmax = -3.0e38f, lcnt = 0.f;
    for (int t = tid; t < Tsz; t += 256) {
        float v = pad[b*Tsz + t] ? 0.f : 1.f;
        s_valid[t] = v;
        float tv = ts[b*Tsz + t];
        lmax = fmaxf(lmax, v > 0.f ? tv : -3.0e38f);
        lcnt += v;
    }
    rmax[tid] = lmax; rsum[tid] = lcnt;
    __syncthreads();
    for (int s = 128; s > 0; s >>= 1) {
        if (tid < s) { rmax[tid] = fmaxf(rmax[tid], rmax[tid+s]); rsum[tid] += rsum[tid+s]; }
        __syncthreads();
    }
    float cnt = fmaxf(rsum[0], 1.f);

    int grp = tid >> 6, c4 = tid & 63;
    const float4* wf4 = (const float4*)(wf + (size_t)b*Tsz*Dsz);
    float4 acc = make_float4(0.f,0.f,0.f,0.f);
    #pragma unroll 4
    for (int t = grp; t < Tsz; t += 4) {
        float4 v = wf4[t*64 + c4];
        float vm = s_valid[t];
        acc.x = fmaf(v.x, vm, acc.x);
        acc.y = fmaf(v.y, vm, acc.y);
        acc.z = fmaf(v.z, vm, acc.z);
        acc.w = fmaf(v.w, vm, acc.w);
    }
    s_acc[grp][c4] = acc;
    __syncthreads();
    if (tid < 64) {
        float4 a = s_acc[0][tid], b1 = s_acc[1][tid], c = s_acc[2][tid], d = s_acc[3][tid];
        float inv = 1.f / cnt;
        float4 r = make_float4((a.x+b1.x+c.x+d.x)*inv, (a.y+b1.y+c.y+d.y)*inv,
                               (a.z+b1.z+c.z+d.z)*inv, (a.w+b1.w+c.w+d.w)*inv);
        ((float4*)(g_q + b*Dsz))[tid] = r;
    }
    if (tid == 0) g_tmax[b] = rmax[0];
}

// ---------------- Kernel 2a: Q = q @ W_Q^T  (C[b,e] = sum_d X[b,d]*W[e,d]) ----------------
__global__ void k_qproj(const float* __restrict__ W) {
    int b0 = blockIdx.x * 4, e = threadIdx.x;
    __shared__ float sx[Dsz*4];       // [d*4 + g]
    for (int i = threadIdx.x; i < Dsz*4; i += 256) {
        int d = i >> 2, g = i & 3;
        sx[i] = g_q[(b0+g)*Dsz + d];
    }
    __syncthreads();
    float a0=0.f, a1=0.f, a2=0.f, a3=0.f;
    const float4* wr = (const float4*)(W + e*Dsz);
    const float4* sx4 = (const float4*)sx;
    #pragma unroll 8
    for (int d4 = 0; d4 < 64; d4++) {
        float4 w = wr[d4];
        float4 x0 = sx4[d4*4+0], x1 = sx4[d4*4+1], x2 = sx4[d4*4+2], x3 = sx4[d4*4+3];
        a0 += w.x*x0.x + w.y*x1.x + w.z*x2.x + w.w*x3.x;
        a1 += w.x*x0.y + w.y*x1.y + w.z*x2.y + w.w*x3.y;
        a2 += w.x*x0.z + w.y*x1.z + w.z*x2.z + w.w*x3.z;
        a3 += w.x*x0.w + w.y*x1.w + w.z*x2.w + w.w*x3.w;
    }
    g_Q[(b0+0)*Dsz+e]=a0; g_Q[(b0+1)*Dsz+e]=a1;
    g_Q[(b0+2)*Dsz+e]=a2; g_Q[(b0+3)*Dsz+e]=a3;
}

// ---------------- Kernel 2b: u = Q @ W_K  (C[b,d] = sum_e X[b,e]*W[e,d]) ----------------
__global__ void k_uproj(const float* __restrict__ W) {
    int b0 = blockIdx.x * 4, dcol = threadIdx.x;
    __shared__ float sx[Dsz*4];       // [e*4 + g]
    for (int i = threadIdx.x; i < Dsz*4; i += 256) {
        int e = i >> 2, g = i & 3;
        sx[i] = g_Q[(b0+g)*Dsz + e];
    }
    __syncthreads();
    const float4* sx4 = (const float4*)sx;
    float a0=0.f, a1=0.f, a2=0.f, a3=0.f;
    #pragma unroll 8
    for (int e = 0; e < Dsz; e++) {
        float w = __ldg(W + e*Dsz + dcol);   // coalesced across threads
        float4 x = sx4[e];
        a0 = fmaf(x.x, w, a0); a1 = fmaf(x.y, w, a1);
        a2 = fmaf(x.z, w, a2); a3 = fmaf(x.w, w, a3);
    }
    g_u[(b0+0)*Dsz+dcol]=a0; g_u[(b0+1)*Dsz+dcol]=a1;
    g_u[(b0+2)*Dsz+dcol]=a2; g_u[(b0+3)*Dsz+dcol]=a3;
}

// ---------------- Kernel 3: fused scores + online decay-softmax + weighted pool y ----------------
__global__ void k3_attn(const float* __restrict__ wf, const float* __restrict__ ts,
                        const unsigned char* __restrict__ pad) {
    int b = blockIdx.x, tid = threadIdx.x;
    int warp = tid >> 5, lane = tid & 31;
    __shared__ float s_lam[Tsz];
    __shared__ float s_valid[Tsz];
    __shared__ float s_m[8], s_Z[8], s_S[8];
    __shared__ __align__(16) float s_y[8*Dsz];

    float tmaxv = g_tmax[b];
    for (int t = tid; t < Tsz; t += 256) {
        float v = pad[b*Tsz + t] ? 0.f : 1.f;
        float dt = fmaxf(tmaxv - ts[b*Tsz + t], 0.f) * (1.f/86400.f);
        s_lam[t] = __expf(-0.5f*dt) * v;
        s_valid[t] = v;
    }
    __syncthreads();

    const float4* u4 = (const float4*)(g_u + b*Dsz);
    float4 ua = u4[lane], ub = u4[lane + 32];
    const float4* wf4 = (const float4*)(wf + (size_t)b*Tsz*Dsz);

    float m = -3.0e38f, Z = 0.f, S = 0.f;
    float4 ya = make_float4(0.f,0.f,0.f,0.f);
    float4 yb = make_float4(0.f,0.f,0.f,0.f);

    #pragma unroll 2
    for (int t = warp; t < Tsz; t += 8) {
        float4 wa = wf4[t*64 + lane];
        float4 wb = wf4[t*64 + 32 + lane];
        float d = wa.x*ua.x + wa.y*ua.y + wa.z*ua.z + wa.w*ua.w
                + wb.x*ub.x + wb.y*ub.y + wb.z*ub.z + wb.w*ub.w;
        #pragma unroll
        for (int o = 16; o > 0; o >>= 1) d += __shfl_xor_sync(0xffffffffu, d, o);
        if (s_valid[t] != 0.f) {               // uniform across warp
            float s  = d * 0.0625f;            // 1/sqrt(256)
            float nm = fmaxf(m, s);
            float sc = __expf(m - nm);
            float e  = __expf(s - nm);
            float g  = s_lam[t] * e;
            Z = Z*sc + e;
            S = S*sc + g;
            ya.x = fmaf(ya.x, sc, g*wa.x); ya.y = fmaf(ya.y, sc, g*wa.y);
            ya.z = fmaf(ya.z, sc, g*wa.z); ya.w = fmaf(ya.w, sc, g*wa.w);
            yb.x = fmaf(yb.x, sc, g*wb.x); yb.y = fmaf(yb.y, sc, g*wb.y);
            yb.z = fmaf(yb.z, sc, g*wb.z); yb.w = fmaf(yb.w, sc, g*wb.w);
            m = nm;
        }
    }

    if (lane == 0) s_m[warp] = m;
    __syncthreads();
    float M = s_m[0];
    #pragma unroll
    for (int w = 1; w < 8; w++) M = fmaxf(M, s_m[w]);
    float scw = __expf(m - M);   // m==-3e38,M finite -> 0; both -3e38 -> 1 on zero accs (ok)
    if (lane == 0) { s_Z[warp] = Z*scw; s_S[warp] = S*scw; }
    float4* sy4 = (float4*)s_y;
    sy4[warp*64 + lane]      = make_float4(ya.x*scw, ya.y*scw, ya.z*scw, ya.w*scw);
    sy4[warp*64 + 32 + lane] = make_float4(yb.x*scw, yb.y*scw, yb.z*scw, yb.w*scw);
    __syncthreads();

    float Zt = 0.f, St = 0.f;
    #pragma unroll
    for (int w = 0; w < 8; w++) { Zt += s_Z[w]; St += s_S[w]; }
    float yv = 0.f;
    #pragma unroll
    for (int w = 0; w < 8; w++) yv += s_y[w*Dsz + tid];
    float denom = St + 1e-8f*Zt;
    float inv = denom > 0.f ? 1.f/denom : 0.f;
    g_y[b*Dsz + tid] = yv * inv;
}

// ---------------- Kernel 4: L = y @ W_V^T + full epilogue + outputs ----------------
__global__ void k4_final(const float* __restrict__ Wv, const float* __restrict__ prevL,
                         const float* __restrict__ prevM, const float* __restrict__ clsw,
                         const float* __restrict__ clsb, float* __restrict__ out) {
    int b0 = blockIdx.x * 4, e = threadIdx.x;
    __shared__ float sx[Dsz*4];
    for (int i = threadIdx.x; i < Dsz*4; i += 256) {
        int d = i >> 2, g = i & 3;
        sx[i] = g_y[(b0+g)*Dsz + d];
    }
    __syncthreads();
    float a0=0.f, a1=0.f, a2=0.f, a3=0.f;
    const float4* wr = (const float4*)(Wv + e*Dsz);
    const float4* sx4 = (const float4*)sx;
    #pragma unroll 8
    for (int d4 = 0; d4 < 64; d4++) {
        float4 w = wr[d4];
        float4 x0 = sx4[d4*4+0], x1 = sx4[d4*4+1], x2 = sx4[d4*4+2], x3 = sx4[d4*4+3];
        a0 += w.x*x0.x + w.y*x1.x + w.z*x2.x + w.w*x3.x;
        a1 += w.x*x0.y + w.y*x1.y + w.z*x2.y + w.w*x3.y;
        a2 += w.x*x0.z + w.y*x1.z + w.z*x2.z + w.w*x3.z;
        a3 += w.x*x0.w + w.y*x1.w + w.z*x2.w + w.w*x3.w;
    }
    float acc[4] = {a0, a1, a2, a3};

    __shared__ float r1[256], r2[256];
    float cw1 = clsw[e], cw2 = clsw[Dsz + e];
    for (int g = 0; g < 4; g++) {
        int b = b0 + g;
        float L  = acc[g];
        float dl = L - prevL[b*Dsz + e];
        r1[e] = dl*dl;
        r2[e] = fmaf(L, cw1, dl*cw2);
        __syncthreads();
        for (int s = 128; s > 0; s >>= 1) {
            if (e < s) { r1[e] += r1[e+s]; r2[e] += r2[e+s]; }
            __syncthreads();
        }
        size_t te = (size_t)OFF_TE + (size_t)b*513;
        out[te + e]            = L;
        out[te + 256 + e]      = dl;
        out[OFF_L + (size_t)b*Dsz + e] = L;
        if (e == 0) {
            float Mt = 0.9f*prevM[b] + 0.1f*sqrtf(r1[0]);
            out[OFF_M + b] = Mt;
            out[te + 512]  = Mt;
            out[b] = r2[0] + Mt*clsw[2*Dsz] + clsb[0];
        }
        __syncthreads();
    }
}

extern "C" void kernel_launch(void* const* d_in, const int* in_sizes, int n_in,
                              void* d_out, int out_size) {
    const float*         wf    = (const float*)d_in[0];
    const float*         ts    = (const float*)d_in[1];
    const float*         prevL = (const float*)d_in[2];
    const float*         prevM = (const float*)d_in[3];
    const unsigned char* pad   = (const unsigned char*)d_in[4];
    const float*         WQ    = (const float*)d_in[5];
    const float*         WK    = (const float*)d_in[6];
    const float*         WV    = (const float*)d_in[7];
    const float*         clsw  = (const float*)d_in[8];
    const float*         clsb  = (const float*)d_in[9];
    float* out = (float*)d_out;

    k1_pool <<<Bsz, 256>>>(wf, ts, pad);
    k_qproj <<<Bsz/4, 256>>>(WQ);
    k_uproj <<<Bsz/4, 256>>>(WK);
    k3_attn <<<Bsz, 256>>>(wf, ts, pad);
    k4_final<<<Bsz/4, 256>>>(WV, prevL, prevM, clsw, clsb, out);
}